// round 16
// baseline (speedup 1.0000x reference)
#include <cuda_runtime.h>
#include <cuda_bf16.h>
#include <mma.h>
#include <math.h>

using namespace nvcuda;

#define N_NODES 50000
#define N_EDGES 800000
#define D 128
#define N_GRAPHS 512
#define EPS 1e-5f
#define CAP 96   // CSR slots per node (deg ~ Poisson(16); P(>96) ~ 1e-40)

// ------------- scratch: device globals, ONLY touched from device code -------
__device__ float g_hA[N_NODES * D];   // layer-0 output fp32 (gather source)
__device__ float g_agg[N_NODES * D];  // fp32 mean-aggregated features
__device__ int   g_cur[N_NODES];      // slot cursor; deg = cur[n] - n*CAP
__device__ int   g_csr[N_NODES * CAP];
__device__ float g_y4[N_NODES * 4];   // 2 deterministic atomic contributions
__device__ float g_psum[N_GRAPHS * 2];
__device__ float g_pmax[N_GRAPHS * 2];
__device__ int   g_pcnt[N_GRAPHS];
// bf16 hi/lo split weights, layout [j][k] (k contiguous, K=256 = [Wl|Wr])
__device__ __nv_bfloat16 g_B0h[128 * 256];
__device__ __nv_bfloat16 g_B0l[128 * 256];
__device__ __nv_bfloat16 g_B1h[128 * 256];
__device__ __nv_bfloat16 g_B1l[128 * 256];
__device__ int   g_idx_is64;

__device__ __forceinline__ int load_idx(const void* p, int i, int is64, int lim) {
    int v = is64 ? (int)((const long long*)p)[i] : ((const int*)p)[i];
    v = v < 0 ? 0 : v;
    return v >= lim ? lim - 1 : v;
}

// ---- setup: dtype detect + inits + bf16 hi/lo weight split ------------------
__global__ void setup_kernel(const unsigned int* __restrict__ ei_raw,
                             const float* __restrict__ Wl0, const float* __restrict__ Wr0,
                             const float* __restrict__ Wl1, const float* __restrict__ Wr1) {
    int idx = blockIdx.x * blockDim.x + threadIdx.x;   // 65536 threads

    if (blockIdx.x == 0 && threadIdx.x < 32) {
        int any = 0;
        for (int i = threadIdx.x; i < 2048; i += 32)
            if (ei_raw[2 * i + 1] != 0u) any = 1;
        unsigned b = __ballot_sync(0xffffffffu, any);
        if (threadIdx.x == 0) g_idx_is64 = b ? 0 : 1;
    }

    if (idx < N_NODES) g_cur[idx] = idx * CAP;
    if (idx < N_GRAPHS) {
        g_psum[idx * 2] = 0.f; g_psum[idx * 2 + 1] = 0.f;
        g_pmax[idx * 2] = __int_as_float(0xff800000);
        g_pmax[idx * 2 + 1] = __int_as_float(0xff800000);
        g_pcnt[idx] = 0;
    }
    for (int i = idx; i < N_NODES * 4; i += 65536) g_y4[i] = 0.f;

    // weight split: layer = idx<32768 ? 0 : 1 ; j, k in [0,256)
    {
        int j = (idx >> 8) & 127, k = idx & 255;
        const float* Wl = (idx < 32768) ? Wl0 : Wl1;
        const float* Wr = (idx < 32768) ? Wr0 : Wr1;
        float v = (k < 128) ? Wl[j * 128 + k] : Wr[j * 128 + (k - 128)];
        __nv_bfloat16 h = __float2bfloat16_rn(v);
        __nv_bfloat16 l = __float2bfloat16_rn(v - __bfloat162float(h));
        int o = j * 256 + k;
        if (idx < 32768) { g_B0h[o] = h; g_B0l[o] = l; }
        else { g_B1h[o] = h; g_B1l[o] = l; }
    }
}

// ---------------- CSR build (single pass; 2 edges/thread, loads up front) ----
__global__ void csr_fill(const void* __restrict__ ei) {
    int is64 = g_idx_is64;
    int t = blockIdx.x * blockDim.x + threadIdx.x;
    int e0 = t * 2;
    if (e0 >= N_EDGES) return;
    int e1 = e0 + 1;
    bool has1 = (e1 < N_EDGES);
    // issue all index loads first (MLP 4)
    int s0 = load_idx(ei, e0, is64, N_NODES);
    int d0 = load_idx(ei, N_EDGES + e0, is64, N_NODES);
    int s1 = has1 ? load_idx(ei, e1, is64, N_NODES) : 0;
    int d1 = has1 ? load_idx(ei, N_EDGES + e1, is64, N_NODES) : 0;
    int slot0 = atomicAdd(&g_cur[d0], 1);
    if (slot0 < d0 * CAP + CAP) g_csr[slot0] = s0;
    if (has1) {
        int slot1 = atomicAdd(&g_cur[d1], 1);
        if (slot1 < d1 * CAP + CAP) g_csr[slot1] = s1;
    }
}

// ------------- mean aggregation: warp per node -> g_agg ---------------------
__global__ void spmm_mean(const float* __restrict__ x_ext, int src_sel) {
    const float* in = (src_sel == 0) ? x_ext : (const float*)g_hA;
    int warp = (blockIdx.x * blockDim.x + threadIdx.x) >> 5;
    int lane = threadIdx.x & 31;
    if (warp >= N_NODES) return;
    int s = warp * CAP;
    int dg = g_cur[warp] - s;
    if (dg > CAP) dg = CAP;
    int e = s + dg;
    float4 acc = make_float4(0.f, 0.f, 0.f, 0.f);
    #pragma unroll 4
    for (int i = s; i < e; i++) {
        int j = g_csr[i];
        float4 v = *(const float4*)(in + (size_t)j * D + lane * 4);
        acc.x += v.x; acc.y += v.y; acc.z += v.z; acc.w += v.w;
    }
    float inv = 1.f / (float)(dg > 1 ? dg : 1);
    acc.x *= inv; acc.y *= inv; acc.z *= inv; acc.w *= inv;
    *(float4*)(g_agg + (size_t)warp * D + lane * 4) = acc;
}

// ---- tensor-core GEMM (wmma bf16, 3-term hi/lo split, fp32 accumulate) ------
// Half-height blocks: 64 rows x 128 cols, 128 threads, 4 warps (2x2), warp
// tile 32x64 (identical fragment geometry, ldm=16 dense tiles). Two 16-wide
// k-stages per barrier pair. 4 CTAs/SM -> 4 independent barrier domains.
// src_sel==0: out = g_hA. src_sel==1: fused layer-2 transform -> y4 atomics.
__device__ __forceinline__ void cvt4(float4 a, uint2& hv, uint2& lv) {
    __nv_bfloat162 h01 = __floats2bfloat162_rn(a.x, a.y);
    __nv_bfloat162 h23 = __floats2bfloat162_rn(a.z, a.w);
    float2 f01 = __bfloat1622float2(h01);
    float2 f23 = __bfloat1622float2(h23);
    __nv_bfloat162 l01 = __floats2bfloat162_rn(a.x - f01.x, a.y - f01.y);
    __nv_bfloat162 l23 = __floats2bfloat162_rn(a.z - f23.x, a.w - f23.y);
    hv.x = *(unsigned*)&h01; hv.y = *(unsigned*)&h23;
    lv.x = *(unsigned*)&l01; lv.y = *(unsigned*)&l23;
}

__global__ void __launch_bounds__(128) gemm_tc(
    const float* __restrict__ x_ext,
    const float* __restrict__ bl,
    const float* __restrict__ bng, const float* __restrict__ bnb,
    const float* __restrict__ bnm, const float* __restrict__ bnv,
    const float* __restrict__ Wl2, const float* __restrict__ Wr2,
    int src_sel)
{
    __shared__ __nv_bfloat16 sAh[2][64 * 16];
    __shared__ __nv_bfloat16 sAl[2][64 * 16];
    __shared__ __nv_bfloat16 sBh[2][128 * 16];
    __shared__ __nv_bfloat16 sBl[2][128 * 16];
    __shared__ float sSc[128], sSh[128];
    __shared__ float sW2[512];

    const float* root = (src_sel == 0) ? x_ext : (const float*)g_hA;
    const __nv_bfloat16* BH = (src_sel == 0) ? g_B0h : g_B1h;
    const __nv_bfloat16* BL = (src_sel == 0) ? g_B0l : g_B1l;

    int tid = threadIdx.x;
    int wid = tid >> 5, lane = tid & 31;
    int wr = wid >> 1, wc = wid & 1;   // warp row (0..1) / col (0..1)
    int base = blockIdx.x * 64;

    if (tid < 128) {
        float s = rsqrtf(bnv[tid] + EPS) * bng[tid];
        sSc[tid] = s;
        sSh[tid] = (bl[tid] - bnm[tid]) * s + bnb[tid];
    }
    if (src_sel != 0) {
        #pragma unroll
        for (int t = 0; t < 4; t++) {
            int i2 = tid + t * 128;
            int o = i2 >> 7, j = i2 & 127;
            sW2[i2] = (o < 2) ? Wl2[o * 128 + j] : Wr2[(o - 2) * 128 + j];
        }
    }

    wmma::fragment<wmma::accumulator, 16, 16, 16, float> C[2][4];
    #pragma unroll
    for (int mt = 0; mt < 2; mt++)
        #pragma unroll
        for (int nt = 0; nt < 4; nt++)
            wmma::fill_fragment(C[mt][nt], 0.f);

    int arow = tid >> 1;               // 0..63
    int kseg = (tid & 1) * 8;

    for (int kp = 0; kp < 8; kp++) {   // 8 double-stages; kt = 2*kp, 2*kp+1
        #pragma unroll
        for (int sub = 0; sub < 2; sub++) {
            int kt = 2 * kp + sub;
            const float* Asrc = (kt < 8) ? (const float*)g_agg : root;
            int ko = (kt & 7) * 16;
            // A: 64 rows x 16 k (fp32 -> bf16 hi/lo)
            {
                int gn = base + arow;
                float4 v0 = make_float4(0.f, 0.f, 0.f, 0.f), v1 = v0;
                if (gn < N_NODES) {
                    const float* p = Asrc + (size_t)gn * D + ko + kseg;
                    v0 = *(const float4*)p;
                    v1 = *(const float4*)(p + 4);
                }
                uint2 h0, l0, h1, l1;
                cvt4(v0, h0, l0);
                cvt4(v1, h1, l1);
                *(uint4*)&sAh[sub][arow * 16 + kseg] = make_uint4(h0.x, h0.y, h1.x, h1.y);
                *(uint4*)&sAl[sub][arow * 16 + kseg] = make_uint4(l0.x, l0.y, l1.x, l1.y);
            }
            // B: 128 j-rows x 16 k (2 rows per thread, pure bf16 copy)
            #pragma unroll
            for (int p = 0; p < 2; p++) {
                int j = arow + p * 64;
                const __nv_bfloat16* ph = BH + (size_t)j * 256 + kt * 16 + kseg;
                const __nv_bfloat16* pl = BL + (size_t)j * 256 + kt * 16 + kseg;
                *(uint4*)&sBh[sub][j * 16 + kseg] = *(const uint4*)ph;
                *(uint4*)&sBl[sub][j * 16 + kseg] = *(const uint4*)pl;
            }
        }
        __syncthreads();

        #pragma unroll
        for (int sub = 0; sub < 2; sub++) {
            wmma::fragment<wmma::matrix_a, 16, 16, 16, __nv_bfloat16, wmma::row_major> ah[2], al[2];
            wmma::fragment<wmma::matrix_b, 16, 16, 16, __nv_bfloat16, wmma::col_major> bh[4], blo[4];
            #pragma unroll
            for (int mt = 0; mt < 2; mt++) {
                wmma::load_matrix_sync(ah[mt], sAh[sub] + (wr * 32 + mt * 16) * 16, 16);
                wmma::load_matrix_sync(al[mt], sAl[sub] + (wr * 32 + mt * 16) * 16, 16);
            }
            #pragma unroll
            for (int nt = 0; nt < 4; nt++) {
                wmma::load_matrix_sync(bh[nt], sBh[sub] + (wc * 64 + nt * 16) * 16, 16);
                wmma::load_matrix_sync(blo[nt], sBl[sub] + (wc * 64 + nt * 16) * 16, 16);
            }
            #pragma unroll
            for (int mt = 0; mt < 2; mt++)
                #pragma unroll
                for (int nt = 0; nt < 4; nt++) {
                    wmma::mma_sync(C[mt][nt], ah[mt], bh[nt], C[mt][nt]);
                    wmma::mma_sync(C[mt][nt], al[mt], bh[nt], C[mt][nt]);
                    wmma::mma_sync(C[mt][nt], ah[mt], blo[nt], C[mt][nt]);
                }
        }
        __syncthreads();
    }

    // epilogue: per-warp 16x16 fp32 patch (reuses sAh space: 4 warps x 1KB)
    float* patch = ((float*)sAh) + wid * 256;
    int prow = lane >> 1;
    int pcol = (lane & 1) * 8;

    if (src_sel == 0) {
        #pragma unroll
        for (int mt = 0; mt < 2; mt++)
            #pragma unroll
            for (int nt = 0; nt < 4; nt++) {
                wmma::store_matrix_sync(patch, C[mt][nt], 16, wmma::mem_row_major);
                __syncwarp();
                int gn = base + wr * 32 + mt * 16 + prow;
                int gc = wc * 64 + nt * 16 + pcol;
                if (gn < N_NODES) {
                    float4 u0 = *(float4*)&patch[prow * 16 + pcol];
                    float4 u1 = *(float4*)&patch[prow * 16 + pcol + 4];
                    float4 w0, w1;
                    w0.x = fmaxf(u0.x * sSc[gc + 0] + sSh[gc + 0], 0.f);
                    w0.y = fmaxf(u0.y * sSc[gc + 1] + sSh[gc + 1], 0.f);
                    w0.z = fmaxf(u0.z * sSc[gc + 2] + sSh[gc + 2], 0.f);
                    w0.w = fmaxf(u0.w * sSc[gc + 3] + sSh[gc + 3], 0.f);
                    w1.x = fmaxf(u1.x * sSc[gc + 4] + sSh[gc + 4], 0.f);
                    w1.y = fmaxf(u1.y * sSc[gc + 5] + sSh[gc + 5], 0.f);
                    w1.z = fmaxf(u1.z * sSc[gc + 6] + sSh[gc + 6], 0.f);
                    w1.w = fmaxf(u1.w * sSc[gc + 7] + sSh[gc + 7], 0.f);
                    float* op = g_hA + (size_t)gn * D + gc;
                    *(float4*)op = w0;
                    *(float4*)(op + 4) = w1;
                }
                __syncwarp();
            }
    } else {
        // fused layer-2 transform: y4 += [Wl2@h ; Wr2@h] partials
        #pragma unroll
        for (int mt = 0; mt < 2; mt++) {
            float p0 = 0.f, p1 = 0.f, p2 = 0.f, p3 = 0.f;
            #pragma unroll
            for (int nt = 0; nt < 4; nt++) {
                wmma::store_matrix_sync(patch, C[mt][nt], 16, wmma::mem_row_major);
                __syncwarp();
                int gc = wc * 64 + nt * 16 + pcol;
                float4 u0 = *(float4*)&patch[prow * 16 + pcol];
                float4 u1 = *(float4*)&patch[prow * 16 + pcol + 4];
                float w[8];
                w[0] = fmaxf(u0.x * sSc[gc + 0] + sSh[gc + 0], 0.f);
                w[1] = fmaxf(u0.y * sSc[gc + 1] + sSh[gc + 1], 0.f);
                w[2] = fmaxf(u0.z * sSc[gc + 2] + sSh[gc + 2], 0.f);
                w[3] = fmaxf(u0.w * sSc[gc + 3] + sSh[gc + 3], 0.f);
                w[4] = fmaxf(u1.x * sSc[gc + 4] + sSh[gc + 4], 0.f);
                w[5] = fmaxf(u1.y * sSc[gc + 5] + sSh[gc + 5], 0.f);
                w[6] = fmaxf(u1.z * sSc[gc + 6] + sSh[gc + 6], 0.f);
                w[7] = fmaxf(u1.w * sSc[gc + 7] + sSh[gc + 7], 0.f);
                #pragma unroll
                for (int c = 0; c < 8; c++) {
                    p0 += w[c] * sW2[0 * 128 + gc + c];
                    p1 += w[c] * sW2[1 * 128 + gc + c];
                    p2 += w[c] * sW2[2 * 128 + gc + c];
                    p3 += w[c] * sW2[3 * 128 + gc + c];
                }
                __syncwarp();
            }
            // combine lane-pair column halves
            p0 += __shfl_xor_sync(0xffffffffu, p0, 1);
            p1 += __shfl_xor_sync(0xffffffffu, p1, 1);
            p2 += __shfl_xor_sync(0xffffffffu, p2, 1);
            p3 += __shfl_xor_sync(0xffffffffu, p3, 1);
            int gn = base + wr * 32 + mt * 16 + prow;
            if ((lane & 1) == 0 && gn < N_NODES) {
                // exactly 2 contributions per element (wc = 0,1): deterministic
                atomicAdd(&g_y4[gn * 4 + 0], p0);
                atomicAdd(&g_y4[gn * 4 + 1], p1);
                atomicAdd(&g_y4[gn * 4 + 2], p2);
                atomicAdd(&g_y4[gn * 4 + 3], p3);
            }
        }
    }
}

// ------- layer 3 aggregate + graph pooling (fused) --------------------------
__device__ __forceinline__ void atomicMaxF(float* addr, float v) {
    if (v >= 0.f) atomicMax((int*)addr, __float_as_int(v));
    else atomicMin((unsigned int*)addr, (unsigned int)__float_as_int(v));
}

__global__ void l3agg_pool(const float* __restrict__ bl2,
                           const void* __restrict__ batch) {
    int is64 = g_idx_is64;
    int n = blockIdx.x * blockDim.x + threadIdx.x;
    if (n >= N_NODES) return;
    int s = n * CAP;
    int dg = g_cur[n] - s;
    if (dg > CAP) dg = CAP;
    int e = s + dg;
    float a0 = 0.f, a1 = 0.f;
    #pragma unroll 4
    for (int i = s; i < e; i++) {
        int j = g_csr[i];
        float2 v = *(const float2*)(g_y4 + j * 4);
        a0 += v.x; a1 += v.y;
    }
    float inv = 1.f / (float)(dg > 1 ? dg : 1);
    float2 r = *(const float2*)(g_y4 + n * 4 + 2);
    float v0 = a0 * inv + bl2[0] + r.x;
    float v1 = a1 * inv + bl2[1] + r.y;

    int g = load_idx(batch, n, is64, N_GRAPHS);
    atomicAdd(&g_psum[g * 2 + 0], v0);
    atomicAdd(&g_psum[g * 2 + 1], v1);
    atomicMaxF(&g_pmax[g * 2 + 0], v0);
    atomicMaxF(&g_pmax[g * 2 + 1], v1);
    atomicAdd(&g_pcnt[g], 1);
}

// ---------------- head MLP ----------------
__global__ void mlp_kernel(const float* __restrict__ mW1, const float* __restrict__ mb1,
                           const float* __restrict__ mW2, const float* __restrict__ mb2,
                           float* __restrict__ out) {
    __shared__ float gg[4];
    __shared__ float hid[128];
    int g = blockIdx.x, t = threadIdx.x;
    if (t < 2) {
        float c = (float)g_pcnt[g];
        float cc = c < 1.f ? 1.f : c;
        gg[t] = g_psum[g * 2 + t] / cc;
        gg[2 + t] = g_pmax[g * 2 + t];
    }
    __syncthreads();
    float s = mb1[t];
    #pragma unroll
    for (int c = 0; c < 4; c++) s += gg[c] * mW1[t * 4 + c];
    hid[t] = fmaxf(s, 0.f);
    __syncthreads();
    if (t < 2) {
        float o = mb2[t];
        #pragma unroll 8
        for (int j = 0; j < 128; j++) o += hid[j] * mW2[t * 128 + j];
        out[g * 2 + t] = o;
    }
}

// ---------------- launch (kernel launches only) -----------------------------
extern "C" void kernel_launch(void* const* d_in, const int* in_sizes, int n_in,
                              void* d_out, int out_size) {
    const float* x     = (const float*)d_in[0];
    const void*  ei    = d_in[1];
    const void*  batch = d_in[2];
    const float* Wl0 = (const float*)d_in[3];
    const float* bl0 = (const float*)d_in[4];
    const float* Wr0 = (const float*)d_in[5];
    const float* Wl1 = (const float*)d_in[6];
    const float* bl1 = (const float*)d_in[7];
    const float* Wr1 = (const float*)d_in[8];
    const float* Wl2 = (const float*)d_in[9];
    const float* bl2 = (const float*)d_in[10];
    const float* Wr2 = (const float*)d_in[11];
    const float* bn0g = (const float*)d_in[12];
    const float* bn0b = (const float*)d_in[13];
    const float* bn0m = (const float*)d_in[14];
    const float* bn0v = (const float*)d_in[15];
    const float* bn1g = (const float*)d_in[16];
    const float* bn1b = (const float*)d_in[17];
    const float* bn1m = (const float*)d_in[18];
    const float* bn1v = (const float*)d_in[19];
    const float* mW1 = (const float*)d_in[20];
    const float* mb1 = (const float*)d_in[21];
    const float* mW2 = (const float*)d_in[22];
    const float* mb2 = (const float*)d_in[23];
    float* out = (float*)d_out;

    const int EB2 = (N_EDGES / 2 + 255) / 256;       // csr_fill: 2 edges/thread
    const int NB = (N_NODES + 255) / 256;            // 196
    const int WB = (N_NODES * 32 + 255) / 256;       // 6250 (warp per node)
    const int GB = (N_NODES + 63) / 64;              // 782 half-height tiles

    setup_kernel<<<256, 256>>>((const unsigned int*)ei, Wl0, Wr0, Wl1, Wr1);
    csr_fill<<<EB2, 256>>>(ei);

    // layer 0: agg(x) -> gemm -> g_hA
    spmm_mean<<<WB, 256>>>(x, 0);
    gemm_tc<<<GB, 128>>>(x, bl0, bn0g, bn0b, bn0m, bn0v, Wl2, Wr2, 0);
    // layer 1: agg(g_hA) -> gemm -> fused layer-2 transform -> y4
    spmm_mean<<<WB, 256>>>(x, 1);
    gemm_tc<<<GB, 128>>>(x, bl1, bn1g, bn1b, bn1m, bn1v, Wl2, Wr2, 1);
    // layer 2 aggregate + pooling
    l3agg_pool<<<NB, 256>>>(bl2, batch);
    mlp_kernel<<<N_GRAPHS, 128>>>(mW1, mb1, mW2, mb2, out);
}

// round 17
// speedup vs baseline: 1.0508x; 1.0508x over previous
#include <cuda_runtime.h>
#include <cuda_bf16.h>
#include <mma.h>
#include <math.h>

using namespace nvcuda;

#define N_NODES 50000
#define N_EDGES 800000
#define D 128
#define N_GRAPHS 512
#define EPS 1e-5f
#define CAP 96   // CSR slots per node (deg ~ Poisson(16); P(>96) ~ 1e-40)

// ------------- scratch: device globals, ONLY touched from device code -------
__device__ float g_hA[N_NODES * D];   // layer-0 output fp32 (gather source)
__device__ float g_agg[N_NODES * D];  // fp32 mean-aggregated features
__device__ int   g_cur[N_NODES];      // slot cursor; deg = cur[n] - n*CAP
__device__ int   g_csr[N_NODES * CAP];
__device__ float g_y4[N_NODES * 4];   // 2 deterministic atomic contributions
__device__ float g_psum[N_GRAPHS * 2];
__device__ float g_pmax[N_GRAPHS * 2];
__device__ int   g_pcnt[N_GRAPHS];
// bf16 hi/lo split weights, layout [j][k] (k contiguous, K=256 = [Wl|Wr])
__device__ __nv_bfloat16 g_B0h[128 * 256];
__device__ __nv_bfloat16 g_B0l[128 * 256];
__device__ __nv_bfloat16 g_B1h[128 * 256];
__device__ __nv_bfloat16 g_B1l[128 * 256];
__device__ int   g_idx_is64;

__device__ __forceinline__ int load_idx(const void* p, int i, int is64, int lim) {
    int v = is64 ? (int)((const long long*)p)[i] : ((const int*)p)[i];
    v = v < 0 ? 0 : v;
    return v >= lim ? lim - 1 : v;
}

#define CP_ASYNC16(dst, src) \
    asm volatile("cp.async.cg.shared.global [%0], [%1], 16;" \
                 :: "r"(dst), "l"(src) : "memory")
#define CP_COMMIT() asm volatile("cp.async.commit_group;" ::: "memory")
#define CP_WAIT0()  asm volatile("cp.async.wait_group 0;" ::: "memory")

// ---- setup: dtype detect + inits + bf16 hi/lo weight split ------------------
__global__ void setup_kernel(const unsigned int* __restrict__ ei_raw,
                             const float* __restrict__ Wl0, const float* __restrict__ Wr0,
                             const float* __restrict__ Wl1, const float* __restrict__ Wr1) {
    int idx = blockIdx.x * blockDim.x + threadIdx.x;   // 65536 threads

    if (blockIdx.x == 0 && threadIdx.x < 32) {
        int any = 0;
        for (int i = threadIdx.x; i < 2048; i += 32)
            if (ei_raw[2 * i + 1] != 0u) any = 1;
        unsigned b = __ballot_sync(0xffffffffu, any);
        if (threadIdx.x == 0) g_idx_is64 = b ? 0 : 1;
    }

    if (idx < N_NODES) g_cur[idx] = idx * CAP;
    if (idx < N_GRAPHS) {
        g_psum[idx * 2] = 0.f; g_psum[idx * 2 + 1] = 0.f;
        g_pmax[idx * 2] = __int_as_float(0xff800000);
        g_pmax[idx * 2 + 1] = __int_as_float(0xff800000);
        g_pcnt[idx] = 0;
    }
    for (int i = idx; i < N_NODES * 4; i += 65536) g_y4[i] = 0.f;

    // weight split: layer = idx<32768 ? 0 : 1 ; j, k in [0,256)
    {
        int j = (idx >> 8) & 127, k = idx & 255;
        const float* Wl = (idx < 32768) ? Wl0 : Wl1;
        const float* Wr = (idx < 32768) ? Wr0 : Wr1;
        float v = (k < 128) ? Wl[j * 128 + k] : Wr[j * 128 + (k - 128)];
        __nv_bfloat16 h = __float2bfloat16_rn(v);
        __nv_bfloat16 l = __float2bfloat16_rn(v - __bfloat162float(h));
        int o = j * 256 + k;
        if (idx < 32768) { g_B0h[o] = h; g_B0l[o] = l; }
        else { g_B1h[o] = h; g_B1l[o] = l; }
    }
}

// ---------------- CSR build (single pass; 2 edges/thread, loads up front) ----
__global__ void csr_fill(const void* __restrict__ ei) {
    int is64 = g_idx_is64;
    int t = blockIdx.x * blockDim.x + threadIdx.x;
    int e0 = t * 2;
    if (e0 >= N_EDGES) return;
    int e1 = e0 + 1;
    bool has1 = (e1 < N_EDGES);
    int s0 = load_idx(ei, e0, is64, N_NODES);
    int d0 = load_idx(ei, N_EDGES + e0, is64, N_NODES);
    int s1 = has1 ? load_idx(ei, e1, is64, N_NODES) : 0;
    int d1 = has1 ? load_idx(ei, N_EDGES + e1, is64, N_NODES) : 0;
    int slot0 = atomicAdd(&g_cur[d0], 1);
    if (slot0 < d0 * CAP + CAP) g_csr[slot0] = s0;
    if (has1) {
        int slot1 = atomicAdd(&g_cur[d1], 1);
        if (slot1 < d1 * CAP + CAP) g_csr[slot1] = s1;
    }
}

// ------------- mean aggregation: warp per node -> g_agg ---------------------
__global__ void spmm_mean(const float* __restrict__ x_ext, int src_sel) {
    const float* in = (src_sel == 0) ? x_ext : (const float*)g_hA;
    int warp = (blockIdx.x * blockDim.x + threadIdx.x) >> 5;
    int lane = threadIdx.x & 31;
    if (warp >= N_NODES) return;
    int s = warp * CAP;
    int dg = g_cur[warp] - s;
    if (dg > CAP) dg = CAP;
    int e = s + dg;
    float4 acc = make_float4(0.f, 0.f, 0.f, 0.f);
    #pragma unroll 4
    for (int i = s; i < e; i++) {
        int j = g_csr[i];
        float4 v = *(const float4*)(in + (size_t)j * D + lane * 4);
        acc.x += v.x; acc.y += v.y; acc.z += v.z; acc.w += v.w;
    }
    float inv = 1.f / (float)(dg > 1 ? dg : 1);
    acc.x *= inv; acc.y *= inv; acc.z *= inv; acc.w *= inv;
    *(float4*)(g_agg + (size_t)warp * D + lane * 4) = acc;
}

// ---- tensor-core GEMM (wmma bf16, 3-term hi/lo split, fp32 accumulate) ------
// 128x128 block, 8 warps (4x2), warp tile 32x64, K=256 in 16 stages of 16,
// ldm=16 dense fragment tiles. Software-pipelined double buffer:
// per stage: prefetch next A (LDG->regs) + next B (cp.async), load cur
// fragments, STS next A, mma, wait+barrier.
// src_sel==0: out = g_hA. src_sel==1: fused layer-2 transform -> y4 atomics.
__device__ __forceinline__ void cvt4(float4 a, uint2& hv, uint2& lv) {
    __nv_bfloat162 h01 = __floats2bfloat162_rn(a.x, a.y);
    __nv_bfloat162 h23 = __floats2bfloat162_rn(a.z, a.w);
    float2 f01 = __bfloat1622float2(h01);
    float2 f23 = __bfloat1622float2(h23);
    __nv_bfloat162 l01 = __floats2bfloat162_rn(a.x - f01.x, a.y - f01.y);
    __nv_bfloat162 l23 = __floats2bfloat162_rn(a.z - f23.x, a.w - f23.y);
    hv.x = *(unsigned*)&h01; hv.y = *(unsigned*)&h23;
    lv.x = *(unsigned*)&l01; lv.y = *(unsigned*)&l23;
}

__global__ void __launch_bounds__(256) gemm_tc(
    const float* __restrict__ x_ext,
    const float* __restrict__ bl,
    const float* __restrict__ bng, const float* __restrict__ bnb,
    const float* __restrict__ bnm, const float* __restrict__ bnv,
    const float* __restrict__ Wl2, const float* __restrict__ Wr2,
    int src_sel)
{
    __shared__ __nv_bfloat16 sAh[2][128 * 16];
    __shared__ __nv_bfloat16 sAl[2][128 * 16];
    __shared__ __nv_bfloat16 sBh[2][128 * 16];
    __shared__ __nv_bfloat16 sBl[2][128 * 16];
    __shared__ float sSc[128], sSh[128];
    __shared__ float sW2[512];

    const float* root = (src_sel == 0) ? x_ext : (const float*)g_hA;
    const __nv_bfloat16* BH = (src_sel == 0) ? g_B0h : g_B1h;
    const __nv_bfloat16* BL = (src_sel == 0) ? g_B0l : g_B1l;

    int tid = threadIdx.x;
    int wid = tid >> 5, lane = tid & 31;
    int wr = wid >> 1, wc = wid & 1;   // warp row/col
    int base = blockIdx.x * 128;

    if (tid < 128) {
        float s = rsqrtf(bnv[tid] + EPS) * bng[tid];
        sSc[tid] = s;
        sSh[tid] = (bl[tid] - bnm[tid]) * s + bnb[tid];
    }
    if (src_sel != 0) {
        #pragma unroll
        for (int t = 0; t < 2; t++) {
            int i2 = tid + t * 256;
            int o = i2 >> 7, j = i2 & 127;
            sW2[i2] = (o < 2) ? Wl2[o * 128 + j] : Wr2[(o - 2) * 128 + j];
        }
    }

    wmma::fragment<wmma::accumulator, 16, 16, 16, float> C[2][4];
    #pragma unroll
    for (int mt = 0; mt < 2; mt++)
        #pragma unroll
        for (int nt = 0; nt < 4; nt++)
            wmma::fill_fragment(C[mt][nt], 0.f);

    int arow = tid >> 1;               // 0..127
    int kseg = (tid & 1) * 8;
    int gn = base + arow;
    bool valid = (gn < N_NODES);

    // smem u32 addresses for cp.async B staging
    unsigned bhAddr[2], blAddr[2];
    #pragma unroll
    for (int b = 0; b < 2; b++) {
        bhAddr[b] = (unsigned)__cvta_generic_to_shared(&sBh[b][arow * 16 + kseg]);
        blAddr[b] = (unsigned)__cvta_generic_to_shared(&sBl[b][arow * 16 + kseg]);
    }
    size_t bOff = (size_t)arow * 256 + kseg;   // + kt*16

    // ---- prologue: stage kt=0 into buffer 0 ----
    {
        const float* Asrc = (const float*)g_agg;     // kt=0 < 8
        float4 v0 = make_float4(0.f, 0.f, 0.f, 0.f), v1 = v0;
        if (valid) {
            const float* p = Asrc + (size_t)gn * D + kseg;
            v0 = *(const float4*)p;
            v1 = *(const float4*)(p + 4);
        }
        CP_ASYNC16(bhAddr[0], BH + bOff);
        CP_ASYNC16(blAddr[0], BL + bOff);
        CP_COMMIT();
        uint2 h0, l0, h1, l1;
        cvt4(v0, h0, l0);
        cvt4(v1, h1, l1);
        *(uint4*)&sAh[0][arow * 16 + kseg] = make_uint4(h0.x, h0.y, h1.x, h1.y);
        *(uint4*)&sAl[0][arow * 16 + kseg] = make_uint4(l0.x, l0.y, l1.x, l1.y);
        CP_WAIT0();
    }
    __syncthreads();

    for (int kt = 0; kt < 16; kt++) {
        int cur = kt & 1, nxt = cur ^ 1;

        // prefetch stage kt+1: A -> regs (LDG), B -> smem[nxt] (cp.async)
        float4 v0 = make_float4(0.f, 0.f, 0.f, 0.f), v1 = v0;
        if (kt < 15) {
            int kn = kt + 1;
            const float* Asrc = (kn < 8) ? (const float*)g_agg : root;
            int ko = (kn & 7) * 16;
            if (valid) {
                const float* p = Asrc + (size_t)gn * D + ko + kseg;
                v0 = *(const float4*)p;
                v1 = *(const float4*)(p + 4);
            }
            CP_ASYNC16(bhAddr[nxt], BH + bOff + kn * 16);
            CP_ASYNC16(blAddr[nxt], BL + bOff + kn * 16);
            CP_COMMIT();
        }

        // load current fragments (all smem reads happen BEFORE the barrier)
        wmma::fragment<wmma::matrix_a, 16, 16, 16, __nv_bfloat16, wmma::row_major> ah[2], al[2];
        #pragma unroll
        for (int mt = 0; mt < 2; mt++) {
            wmma::load_matrix_sync(ah[mt], sAh[cur] + (wr * 32 + mt * 16) * 16, 16);
            wmma::load_matrix_sync(al[mt], sAl[cur] + (wr * 32 + mt * 16) * 16, 16);
        }

        // STS next A (targets smem[nxt]; last read at kt-1, barrier since)
        if (kt < 15) {
            uint2 h0, l0, h1, l1;
            cvt4(v0, h0, l0);
            cvt4(v1, h1, l1);
            *(uint4*)&sAh[nxt][arow * 16 + kseg] = make_uint4(h0.x, h0.y, h1.x, h1.y);
            *(uint4*)&sAl[nxt][arow * 16 + kseg] = make_uint4(l0.x, l0.y, l1.x, l1.y);
        }

        // mma in two nt-halves (limits live B fragments)
        #pragma unroll
        for (int half = 0; half < 2; half++) {
            wmma::fragment<wmma::matrix_b, 16, 16, 16, __nv_bfloat16, wmma::col_major> bh[2], blo[2];
            #pragma unroll
            for (int q = 0; q < 2; q++) {
                int nt = half * 2 + q;
                wmma::load_matrix_sync(bh[q], sBh[cur] + (wc * 64 + nt * 16) * 16, 16);
                wmma::load_matrix_sync(blo[q], sBl[cur] + (wc * 64 + nt * 16) * 16, 16);
            }
            #pragma unroll
            for (int mt = 0; mt < 2; mt++)
                #pragma unroll
                for (int q = 0; q < 2; q++) {
                    int nt = half * 2 + q;
                    wmma::mma_sync(C[mt][nt], ah[mt], bh[q], C[mt][nt]);
                    wmma::mma_sync(C[mt][nt], al[mt], bh[q], C[mt][nt]);
                    wmma::mma_sync(C[mt][nt], ah[mt], blo[q], C[mt][nt]);
                }
        }

        CP_WAIT0();
        __syncthreads();
    }

    // epilogue: per-warp 16x16 fp32 patch (reuses sAh space: 8KB)
    float* patch = ((float*)sAh) + wid * 256;
    int prow = lane >> 1;
    int pcol = (lane & 1) * 8;

    if (src_sel == 0) {
        #pragma unroll
        for (int mt = 0; mt < 2; mt++)
            #pragma unroll
            for (int nt = 0; nt < 4; nt++) {
                wmma::store_matrix_sync(patch, C[mt][nt], 16, wmma::mem_row_major);
                __syncwarp();
                int go = base + wr * 32 + mt * 16 + prow;
                int gc = wc * 64 + nt * 16 + pcol;
                if (go < N_NODES) {
                    float4 u0 = *(float4*)&patch[prow * 16 + pcol];
                    float4 u1 = *(float4*)&patch[prow * 16 + pcol + 4];
                    float4 w0, w1;
                    w0.x = fmaxf(u0.x * sSc[gc + 0] + sSh[gc + 0], 0.f);
                    w0.y = fmaxf(u0.y * sSc[gc + 1] + sSh[gc + 1], 0.f);
                    w0.z = fmaxf(u0.z * sSc[gc + 2] + sSh[gc + 2], 0.f);
                    w0.w = fmaxf(u0.w * sSc[gc + 3] + sSh[gc + 3], 0.f);
                    w1.x = fmaxf(u1.x * sSc[gc + 4] + sSh[gc + 4], 0.f);
                    w1.y = fmaxf(u1.y * sSc[gc + 5] + sSh[gc + 5], 0.f);
                    w1.z = fmaxf(u1.z * sSc[gc + 6] + sSh[gc + 6], 0.f);
                    w1.w = fmaxf(u1.w * sSc[gc + 7] + sSh[gc + 7], 0.f);
                    float* op = g_hA + (size_t)go * D + gc;
                    *(float4*)op = w0;
                    *(float4*)(op + 4) = w1;
                }
                __syncwarp();
            }
    } else {
        // fused layer-2 transform: y4 += [Wl2@h ; Wr2@h] partials
        #pragma unroll
        for (int mt = 0; mt < 2; mt++) {
            float p0 = 0.f, p1 = 0.f, p2 = 0.f, p3 = 0.f;
            #pragma unroll
            for (int nt = 0; nt < 4; nt++) {
                wmma::store_matrix_sync(patch, C[mt][nt], 16, wmma::mem_row_major);
                __syncwarp();
                int gc = wc * 64 + nt * 16 + pcol;
                float4 u0 = *(float4*)&patch[prow * 16 + pcol];
                float4 u1 = *(float4*)&patch[prow * 16 + pcol + 4];
                float w[8];
                w[0] = fmaxf(u0.x * sSc[gc + 0] + sSh[gc + 0], 0.f);
                w[1] = fmaxf(u0.y * sSc[gc + 1] + sSh[gc + 1], 0.f);
                w[2] = fmaxf(u0.z * sSc[gc + 2] + sSh[gc + 2], 0.f);
                w[3] = fmaxf(u0.w * sSc[gc + 3] + sSh[gc + 3], 0.f);
                w[4] = fmaxf(u1.x * sSc[gc + 4] + sSh[gc + 4], 0.f);
                w[5] = fmaxf(u1.y * sSc[gc + 5] + sSh[gc + 5], 0.f);
                w[6] = fmaxf(u1.z * sSc[gc + 6] + sSh[gc + 6], 0.f);
                w[7] = fmaxf(u1.w * sSc[gc + 7] + sSh[gc + 7], 0.f);
                #pragma unroll
                for (int c = 0; c < 8; c++) {
                    p0 += w[c] * sW2[0 * 128 + gc + c];
                    p1 += w[c] * sW2[1 * 128 + gc + c];
                    p2 += w[c] * sW2[2 * 128 + gc + c];
                    p3 += w[c] * sW2[3 * 128 + gc + c];
                }
                __syncwarp();
            }
            // combine lane-pair column halves
            p0 += __shfl_xor_sync(0xffffffffu, p0, 1);
            p1 += __shfl_xor_sync(0xffffffffu, p1, 1);
            p2 += __shfl_xor_sync(0xffffffffu, p2, 1);
            p3 += __shfl_xor_sync(0xffffffffu, p3, 1);
            int go = base + wr * 32 + mt * 16 + prow;
            if ((lane & 1) == 0 && go < N_NODES) {
                // exactly 2 contributions per element (wc = 0,1): deterministic
                atomicAdd(&g_y4[go * 4 + 0], p0);
                atomicAdd(&g_y4[go * 4 + 1], p1);
                atomicAdd(&g_y4[go * 4 + 2], p2);
                atomicAdd(&g_y4[go * 4 + 3], p3);
            }
        }
    }
}

// ------- layer 3 aggregate + graph pooling (fused) --------------------------
__device__ __forceinline__ void atomicMaxF(float* addr, float v) {
    if (v >= 0.f) atomicMax((int*)addr, __float_as_int(v));
    else atomicMin((unsigned int*)addr, (unsigned int)__float_as_int(v));
}

__global__ void l3agg_pool(const float* __restrict__ bl2,
                           const void* __restrict__ batch) {
    int is64 = g_idx_is64;
    int n = blockIdx.x * blockDim.x + threadIdx.x;
    if (n >= N_NODES) return;
    int s = n * CAP;
    int dg = g_cur[n] - s;
    if (dg > CAP) dg = CAP;
    int e = s + dg;
    float a0 = 0.f, a1 = 0.f;
    #pragma unroll 4
    for (int i = s; i < e; i++) {
        int j = g_csr[i];
        float2 v = *(const float2*)(g_y4 + j * 4);
        a0 += v.x; a1 += v.y;
    }
    float inv = 1.f / (float)(dg > 1 ? dg : 1);
    float2 r = *(const float2*)(g_y4 + n * 4 + 2);
    float v0 = a0 * inv + bl2[0] + r.x;
    float v1 = a1 * inv + bl2[1] + r.y;

    int g = load_idx(batch, n, is64, N_GRAPHS);
    atomicAdd(&g_psum[g * 2 + 0], v0);
    atomicAdd(&g_psum[g * 2 + 1], v1);
    atomicMaxF(&g_pmax[g * 2 + 0], v0);
    atomicMaxF(&g_pmax[g * 2 + 1], v1);
    atomicAdd(&g_pcnt[g], 1);
}

// ---------------- head MLP ----------------
__global__ void mlp_kernel(const float* __restrict__ mW1, const float* __restrict__ mb1,
                           const float* __restrict__ mW2, const float* __restrict__ mb2,
                           float* __restrict__ out) {
    __shared__ float gg[4];
    __shared__ float hid[128];
    int g = blockIdx.x, t = threadIdx.x;
    if (t < 2) {
        float c = (float)g_pcnt[g];
        float cc = c < 1.f ? 1.f : c;
        gg[t] = g_psum[g * 2 + t] / cc;
        gg[2 + t] = g_pmax[g * 2 + t];
    }
    __syncthreads();
    float s = mb1[t];
    #pragma unroll
    for (int c = 0; c < 4; c++) s += gg[c] * mW1[t * 4 + c];
    hid[t] = fmaxf(s, 0.f);
    __syncthreads();
    if (t < 2) {
        float o = mb2[t];
        #pragma unroll 8
        for (int j = 0; j < 128; j++) o += hid[j] * mW2[t * 128 + j];
        out[g * 2 + t] = o;
    }
}

// ---------------- launch (kernel launches only) -----------------------------
extern "C" void kernel_launch(void* const* d_in, const int* in_sizes, int n_in,
                              void* d_out, int out_size) {
    const float* x     = (const float*)d_in[0];
    const void*  ei    = d_in[1];
    const void*  batch = d_in[2];
    const float* Wl0 = (const float*)d_in[3];
    const float* bl0 = (const float*)d_in[4];
    const float* Wr0 = (const float*)d_in[5];
    const float* Wl1 = (const float*)d_in[6];
    const float* bl1 = (const float*)d_in[7];
    const float* Wr1 = (const float*)d_in[8];
    const float* Wl2 = (const float*)d_in[9];
    const float* bl2 = (const float*)d_in[10];
    const float* Wr2 = (const float*)d_in[11];
    const float* bn0g = (const float*)d_in[12];
    const float* bn0b = (const float*)d_in[13];
    const float* bn0m = (const float*)d_in[14];
    const float* bn0v = (const float*)d_in[15];
    const float* bn1g = (const float*)d_in[16];
    const float* bn1b = (const float*)d_in[17];
    const float* bn1m = (const float*)d_in[18];
    const float* bn1v = (const float*)d_in[19];
    const float* mW1 = (const float*)d_in[20];
    const float* mb1 = (const float*)d_in[21];
    const float* mW2 = (const float*)d_in[22];
    const float* mb2 = (const float*)d_in[23];
    float* out = (float*)d_out;

    const int EB2 = (N_EDGES / 2 + 255) / 256;       // csr_fill: 2 edges/thread
    const int NB = (N_NODES + 255) / 256;            // 196
    const int WB = (N_NODES * 32 + 255) / 256;       // 6250 (warp per node)
    const int GB = (N_NODES + 127) / 128;            // 391

    setup_kernel<<<256, 256>>>((const unsigned int*)ei, Wl0, Wr0, Wl1, Wr1);
    csr_fill<<<EB2, 256>>>(ei);

    // layer 0: agg(x) -> gemm -> g_hA
    spmm_mean<<<WB, 256>>>(x, 0);
    gemm_tc<<<GB, 256>>>(x, bl0, bn0g, bn0b, bn0m, bn0v, Wl2, Wr2, 0);
    // layer 1: agg(g_hA) -> gemm -> fused layer-2 transform -> y4
    spmm_mean<<<WB, 256>>>(x, 1);
    gemm_tc<<<GB, 256>>>(x, bl1, bn1g, bn1b, bn1m, bn1v, Wl2, Wr2, 1);
    // layer 2 aggregate + pooling
    l3agg_pool<<<NB, 256>>>(bl2, batch);
    mlp_kernel<<<N_GRAPHS, 128>>>(mW1, mb1, mW2, mb2, out);
}